// round 9
// baseline (speedup 1.0000x reference)
#include <cuda_runtime.h>
#include <cuda_bf16.h>

#define BATCH 16
#define MP 30      // max people
#define NJ 17      // joints
#define AD 17      // ae tag dim
#define RES 512
#define RR (RES*RES)

#define JPI   (MP * NJ)        // 510 joints per image
#define SUBS  9                // CTAs per image
#define TPS   57               // joint-tasks per sub-CTA (9*57 = 513 >= 510)
#define GRID_CTAS (BATCH * SUBS)   // 144
#define BLOCK_THREADS 512
#define NPAIR 435              // MP*(MP-1)/2 off-diagonal unordered pairs

// per-(image,sub) partial slabs -- every slot written unconditionally, no zeroing needed
__device__ float g_sum_part[BATCH * SUBS * MP * AD];  // masked tag sums
__device__ float g_sq_part [BATCH * SUBS * MP];       // per-person sum of sqv
__device__ float g_cnt_part[BATCH * SUBS * MP];       // per-person valid counts
// self-resetting grid barrier (gen monotonic across graph replays)
__device__ unsigned g_bar_count = 0;
__device__ volatile unsigned g_bar_gen = 0;

__global__ __launch_bounds__(BLOCK_THREADS, 1)
void ae_fused_kernel(const float* __restrict__ tags,
                     const int*   __restrict__ joints,
                     float*       __restrict__ out)
{
    const int c   = blockIdx.x;
    const int tid = threadIdx.x;
    const int b   = c / SUBS;              // image for PHASE A only
    const int sub = c % SUBS;
    const unsigned FULL = 0xffffffffu;

    // ---------------- Phase A: warp-per-joint gather + per-CTA partials ----
    __shared__ float sh_sum[MP][AD];
    __shared__ float sh_sq[MP];
    __shared__ float sh_cnt[MP];

    for (int i = tid; i < MP * AD; i += BLOCK_THREADS) ((float*)sh_sum)[i] = 0.0f;
    if (tid < MP) { sh_sq[tid] = 0.0f; sh_cnt[tid] = 0.0f; }
    __syncthreads();

    const int wid  = tid >> 5;
    const int lane = tid & 31;

    for (int t = wid; t < TPS; t += BLOCK_THREADS / 32) {
        const int jg = sub * TPS + t;          // joint index within image
        if (jg >= JPI) break;
        const int m = jg / NJ;

        const int base = (b * JPI + jg) * 2;
        const int idx = __ldg(&joints[base + 0]);
        const int vis = __ldg(&joints[base + 1]);   // warp-uniform

        if (vis > 0) {
            int off = idx % RR;
            if (off < 0) off += RR;
            const int x = off % RES;           // first spatial axis (torch convention)
            const int y = off / RES;

            float v = 0.0f;
            if (lane < AD)
                v = __ldg(tags + (size_t)b * AD * RR + (size_t)lane * RR
                               + (size_t)x * RES + y);
            float s1 = v, s2 = v * v;
            #pragma unroll
            for (int o = 16; o > 0; o >>= 1) {
                s1 += __shfl_down_sync(FULL, s1, o);
                s2 += __shfl_down_sync(FULL, s2, o);
            }
            if (lane < AD) atomicAdd(&sh_sum[m][lane], v);
            if (lane == 0) {
                // sum_{d1,d2}(t_d1 - t_d2)^2 = 2*D*S2 - 2*S1^2
                atomicAdd(&sh_sq[m],  2.0f * (float)AD * s2 - 2.0f * s1 * s1);
                atomicAdd(&sh_cnt[m], 1.0f);
            }
        }
    }
    __syncthreads();

    // write this CTA's partial slab (coalesced, unconditional)
    {
        float* dst = g_sum_part + (size_t)c * MP * AD;
        for (int i = tid; i < MP * AD; i += BLOCK_THREADS) dst[i] = ((float*)sh_sum)[i];
        if (tid < MP) {
            g_sq_part [c * MP + tid] = sh_sq[tid];
            g_cnt_part[c * MP + tid] = sh_cnt[tid];
        }
    }
    __syncthreads();

    // ---------------- grid barrier (sense-reversing, self-resetting) -------
    if (tid == 0) {
        __threadfence();                       // publish slab writes
        unsigned gen = g_bar_gen;              // read phase BEFORE arriving
        unsigned t = atomicAdd(&g_bar_count, 1u);
        if (t == GRID_CTAS - 1) {
            g_bar_count = 0;                   // reset for next replay
            __threadfence();
            g_bar_gen = gen + 1;               // release
        } else if (c < BATCH) {
            while (g_bar_gen == gen) { }       // only reducing CTAs spin
        }
        __threadfence();                       // acquire
    }
    __syncthreads();

    if (c >= BATCH) return;                    // non-reducers exit after arriving

    // ---------------- Phase B: thin per-image reduction ---------------------
    const int bb = c;                          // *** image index = CTA index ***

    __shared__ float mean_s[MP][AD];
    __shared__ float cnt_s[MP];
    __shared__ float pv[MP];
    __shared__ float sqsum_s[MP];
    __shared__ float ntags_s;
    __shared__ float push_acc;

    if (tid == 0) push_acc = 0.0f;

    if (tid < MP) {
        float cs = 0.0f, qs = 0.0f;
        #pragma unroll
        for (int s = 0; s < SUBS; s++) {
            cs += g_cnt_part[(bb * SUBS + s) * MP + tid];
            qs += g_sq_part [(bb * SUBS + s) * MP + tid];
        }
        cnt_s[tid]   = cs;
        sqsum_s[tid] = qs;
        pv[tid]      = (cs > 0.0f) ? 1.0f : 0.0f;
    }
    __syncthreads();

    if (tid < MP * AD) {
        const int m = tid / AD;
        float sm = 0.0f;
        #pragma unroll
        for (int s = 0; s < SUBS; s++)
            sm += g_sum_part[((size_t)(bb * SUBS + s)) * MP * AD + tid];
        mean_s[m][tid % AD] = sm / fmaxf(cnt_s[m], 1.0f);
    }

    if (tid == 0) {
        float nt = 0.0f, pl = 0.0f;
        #pragma unroll
        for (int m = 0; m < MP; m++) {
            nt += pv[m];
            pl += pv[m] * sqsum_s[m] / ((float)(AD * AD) * fmaxf(cnt_s[m], 1.0f));
        }
        ntags_s = nt;
        out[BATCH + bb] = pl / fmaxf(nt, 1.0f);   // pull[16]
    }
    __syncthreads();

    // off-diagonal pairs only (m1 < m2); diagonal contributes n_tags analytically
    float acc = 0.0f;
    if (tid < NPAIR) {
        int rem = tid, m1 = 0;
        while (rem >= MP - 1 - m1) { rem -= MP - 1 - m1; m1++; }
        const int m2 = m1 + 1 + rem;
        const float w = pv[m1] * pv[m2];
        if (w != 0.0f) {
            float s = 0.0f;
            #pragma unroll
            for (int d = 0; d < AD; d++) {
                float df = mean_s[m1][d] - mean_s[m2][d];
                s += __expf(-df * df);
            }
            acc = s * (1.0f / (float)AD);
        }
    }
    #pragma unroll
    for (int o = 16; o > 0; o >>= 1)
        acc += __shfl_down_sync(FULL, acc, o);
    if ((tid & 31) == 0 && tid < NPAIR + 31) atomicAdd(&push_acc, acc);
    __syncthreads();

    if (tid == 0) {
        const float nt = ntags_s;
        const float denom = fmaxf(nt, 1.0f);
        // ordered off-diag sum = 2 * unordered; diagonal sum = nt
        const float push = (nt >= 2.0f) ? ((2.0f * push_acc + nt) / (denom * denom))
                                        : 0.0f;
        out[bb] = push;                           // push[16]
    }
}

extern "C" void kernel_launch(void* const* d_in, const int* in_sizes, int n_in,
                              void* d_out, int out_size)
{
    const float* tags   = (const float*)d_in[0];
    const int*   joints = (const int*)d_in[1];
    float*       out    = (float*)d_out;

    ae_fused_kernel<<<GRID_CTAS, BLOCK_THREADS>>>(tags, joints, out);
}

// round 10
// speedup vs baseline: 1.9940x; 1.9940x over previous
#include <cuda_runtime.h>
#include <cuda_bf16.h>

#define BATCH 16
#define MP 30      // max people
#define NJ 17      // joints
#define AD 17      // ae tag dim
#define RES 512
#define RR (RES*RES)

#define JPI   (MP * NJ)                 // 510 joints per image
#define ROWP  20                        // padded floats per joint row (80B, 16B-aligned)
#define TOTAL_ELEMS (BATCH * JPI * AD)  // 147456 gather tasks
#define NPAIR 435                       // MP*(MP-1)/2 unordered off-diagonal pairs

// scratch: masked gathered tags, padded rows: [b*JPI + jj][ROWP]
__device__ __align__(16) float g_scratch[BATCH * JPI * ROWP];

// ---------------------------------------------------------------------------
// Kernel 1: scattered gather, one thread per (b,m,j,d), spread over all SMs.
// Invisible joints contribute exactly 0 downstream -> skip the load, store 0.
// ---------------------------------------------------------------------------
__global__ __launch_bounds__(256)
void ae_gather_kernel(const float* __restrict__ tags,
                      const int*   __restrict__ joints)
{
    int e = blockIdx.x * blockDim.x + threadIdx.x;
    if (e >= TOTAL_ELEMS) return;

    const int d  = e % AD;
    const int jj = e / AD;               // global joint id in [0, B*JPI)
    const int b  = jj / JPI;

    const int idx = __ldg(&joints[jj * 2 + 0]);
    const int vis = __ldg(&joints[jj * 2 + 1]);

    float v = 0.0f;
    if (vis > 0) {
        int off = idx % RR;
        if (off < 0) off += RR;
        const int x = off % RES;         // first spatial axis (torch convention)
        const int y = off / RES;
        v = __ldg(tags + (size_t)b * AD * RR + (size_t)d * RR
                       + (size_t)x * RES + y);
    }
    g_scratch[(size_t)jj * ROWP + d] = v;
}

// ---------------------------------------------------------------------------
// Kernel 2: per-image reduction (vectorized scratch reads, fast exp).
// ---------------------------------------------------------------------------
__global__ __launch_bounds__(512, 1)
void ae_reduce_kernel(const int* __restrict__ joints,
                      float*     __restrict__ out)
{
    const int b   = blockIdx.x;
    const int tid = threadIdx.x;
    const unsigned FULL = 0xffffffffu;

    __shared__ float t_s[MP][NJ][AD];   // masked tag vectors
    __shared__ float sqv[MP][NJ];       // valid * sum_{d1,d2}(t_d1-t_d2)^2
    __shared__ float validf[MP][NJ];
    __shared__ float safe_cnt[MP];
    __shared__ float pullp[MP];
    __shared__ float pv[MP];
    __shared__ float mean_s[MP][AD];
    __shared__ float ntags_s;
    __shared__ float pull_s;
    __shared__ float push_acc;

    const int* jt_b = joints + b * JPI * 2;

    if (tid == 0) push_acc = 0.0f;

    // ---- per-joint: 4x float4 + 1 scalar from padded scratch ----
    if (tid < JPI) {
        const int m = tid / NJ;
        const int j = tid % NJ;
        const int vis = jt_b[tid * 2 + 1];
        const float valid = (vis > 0) ? 1.0f : 0.0f;

        const float4* p4 = (const float4*)(g_scratch + ((size_t)(b * JPI + tid)) * ROWP);
        float4 r0 = __ldg(p4 + 0);
        float4 r1 = __ldg(p4 + 1);
        float4 r2 = __ldg(p4 + 2);
        float4 r3 = __ldg(p4 + 3);
        float  rl = __ldg((const float*)(p4 + 4));   // element 16

        float va[AD] = { r0.x, r0.y, r0.z, r0.w,
                         r1.x, r1.y, r1.z, r1.w,
                         r2.x, r2.y, r2.z, r2.w,
                         r3.x, r3.y, r3.z, r3.w, rl };

        float s1 = 0.0f, s2 = 0.0f;
        #pragma unroll
        for (int d = 0; d < AD; d++) {
            s1 += va[d];
            s2 += va[d] * va[d];
            t_s[m][j][d] = va[d];        // already masked by gather
        }
        // valid * sum_{d1,d2}(t_d1 - t_d2)^2 = valid * (2*D*S2 - 2*S1^2)
        sqv[m][j]    = valid * (2.0f * (float)AD * s2 - 2.0f * s1 * s1);
        validf[m][j] = valid;
    }
    __syncthreads();

    // ---- per-person counts + pull_p ----
    if (tid < MP) {
        const int m = tid;
        float cnt = 0.0f, sq = 0.0f;
        #pragma unroll
        for (int j = 0; j < NJ; j++) {
            cnt += validf[m][j];
            sq  += sqv[m][j];
        }
        float scn = fmaxf(cnt, 1.0f);
        safe_cnt[m] = scn;
        float person_valid = (cnt > 0.0f) ? 1.0f : 0.0f;
        pv[m]    = person_valid;
        pullp[m] = person_valid * sq / ((float)(AD * AD) * scn);
    }
    __syncthreads();

    // ---- per-person mean tag: one thread per (m,d) ----
    if (tid < MP * AD) {
        const int m = tid / AD;
        const int d = tid % AD;
        float s = 0.0f;
        #pragma unroll
        for (int j = 0; j < NJ; j++) s += t_s[m][j][d];
        mean_s[m][d] = s / safe_cnt[m];
    }

    // ---- n_tags + pull scalar ----
    if (tid == 0) {
        float nt = 0.0f, pl = 0.0f;
        #pragma unroll
        for (int m = 0; m < MP; m++) { nt += pv[m]; pl += pullp[m]; }
        ntags_s = nt;
        pull_s  = pl / fmaxf(nt, 1.0f);
    }
    __syncthreads();

    // ---- push: 435 unordered off-diagonal pairs, fast exp ----
    float acc = 0.0f;
    if (tid < NPAIR) {
        int rem = tid, m1 = 0;
        while (rem >= MP - 1 - m1) { rem -= MP - 1 - m1; m1++; }
        const int m2 = m1 + 1 + rem;
        const float w = pv[m1] * pv[m2];
        if (w != 0.0f) {
            float s = 0.0f;
            #pragma unroll
            for (int d = 0; d < AD; d++) {
                float df = mean_s[m1][d] - mean_s[m2][d];
                s += __expf(-df * df);   // MUFU.EX2 path
            }
            acc = s * (1.0f / (float)AD);
        }
    }
    #pragma unroll
    for (int o = 16; o > 0; o >>= 1)
        acc += __shfl_down_sync(FULL, acc, o);
    if ((tid & 31) == 0 && tid < NPAIR) atomicAdd(&push_acc, acc);
    __syncthreads();

    if (tid == 0) {
        const float nt = ntags_s;
        const float denom = fmaxf(nt, 1.0f);
        // ordered off-diag sum = 2 * unordered; diagonal sum = nt (exp(0)=1)
        const float push = (nt >= 2.0f) ? ((2.0f * push_acc + nt) / (denom * denom))
                                        : 0.0f;
        out[b]         = push;   // push[16]
        out[BATCH + b] = pull_s; // pull[16]
    }
}

extern "C" void kernel_launch(void* const* d_in, const int* in_sizes, int n_in,
                              void* d_out, int out_size)
{
    const float* tags   = (const float*)d_in[0];
    const int*   joints = (const int*)d_in[1];
    float*       out    = (float*)d_out;

    const int threads = 256;
    const int blocks  = (TOTAL_ELEMS + threads - 1) / threads;  // 576
    ae_gather_kernel<<<blocks, threads>>>(tags, joints);
    ae_reduce_kernel<<<BATCH, 512>>>(joints, out);
}